// round 1
// baseline (speedup 1.0000x reference)
#include <cuda_runtime.h>
#include <math.h>
#include <stdint.h>

// ---------------- problem constants ----------------
#define BB    4
#define SS    2048
#define HIDC  768
#define NH    6
#define HD    64
#define AHSZ  384
#define KW    9
#define MROWS (BB*SS)      // 8192
#define NZ    (BB*NH)      // 24
#define HK    (NH*KW)      // 54

// ---------------- GEMM tile config ----------------
#define BM  128
#define BN  64
#define BKD 16
#define TM  8
#define TN  4
#define NTHR 256

// ---------------- scratch (__device__ globals; no allocation allowed) ----------------
__device__ float g_q   [MROWS*AHSZ];
__device__ float g_k   [MROWS*AHSZ];
__device__ float g_v   [MROWS*AHSZ];
__device__ float g_dw  [MROWS*HIDC];
__device__ float g_ks  [MROWS*AHSZ];
__device__ float g_conv[MROWS*AHSZ];
__device__ float g_logits[MROWS*HK];
__device__ float g_mx  [NZ*SS];
__device__ float g_inv [NZ*SS];
// fallbacks in case harness out buffer only holds a subset of the tuple
__device__ float g_attn_fb[MROWS*AHSZ];
__device__ float g_sco_fb [(size_t)NZ*SS*SS];

enum { MODE_NN = 0, MODE_NT = 1, MODE_SCORES = 2, MODE_PV = 3 };

// ---------------- generic tiled SGEMM ----------------
// C[m,n] = sum_k A'[m,k] * W'[k,n]  (+bias / +mask / *rowscale depending on MODE)
// NN: W indexed [k*ldw + n];  NT/SCORES: W indexed [n*ldw + k]
// SCORES: batched over z=b*NH+h, alpha=0.125, adds attention_mask[b, n]
// PV: batched, A-load transformed by exp(x - mx[m]), epilogue scaled by inv[m]
template <int MODE>
__global__ void __launch_bounds__(NTHR) gemm_k(
    const float* __restrict__ Ab, const float* __restrict__ Wb,
    const float* __restrict__ bias, float* __restrict__ Cb,
    int Kdim, int lda, int ldw, int ldc,
    const float* __restrict__ p1, const float* __restrict__ p2)
{
    __shared__ float As[BKD][BM + 4];
    __shared__ float Bs[BKD][BN + 4];

    const int tid = threadIdx.x;
    const int tx  = tid & 15;   // 16 thread cols
    const int ty  = tid >> 4;   // 16 thread rows
    const int m0  = blockIdx.y * BM;
    const int n0  = blockIdx.x * BN;

    const float* A = Ab;
    const float* W = Wb;
    float* C = Cb;
    const float* maskp = nullptr;
    const float* mxp   = nullptr;
    const float* invp  = nullptr;

    if constexpr (MODE == MODE_SCORES) {
        const int z = blockIdx.z, b = z / NH, h = z % NH;
        A = Ab + (size_t)b * SS * AHSZ + h * HD;
        W = Wb + (size_t)b * SS * AHSZ + h * HD;
        C = Cb + (size_t)z * SS * SS;
        maskp = p1 + (size_t)b * SS;
        lda = AHSZ; ldw = AHSZ; ldc = SS; Kdim = HD;
    }
    if constexpr (MODE == MODE_PV) {
        const int z = blockIdx.z, b = z / NH, h = z % NH;
        A = Ab + (size_t)z * SS * SS;
        W = Wb + (size_t)b * SS * AHSZ + h * HD;
        C = Cb + (size_t)b * SS * AHSZ + h * HD;
        mxp  = p1 + (size_t)z * SS;
        invp = p2 + (size_t)z * SS;
        lda = SS; ldw = AHSZ; ldc = AHSZ; Kdim = SS;
    }

    float acc[TM][TN];
#pragma unroll
    for (int i = 0; i < TM; i++)
#pragma unroll
        for (int j = 0; j < TN; j++) acc[i][j] = 0.f;

    for (int k0 = 0; k0 < Kdim; k0 += BKD) {
        // --- load A tile (BM x BKD), store transposed into As[col][row] ---
#pragma unroll
        for (int i = 0; i < 2; i++) {
            const int f   = tid * 2 + i;      // 0..511
            const int row = f >> 2;           // 0..127
            const int col = (f & 3) * 4;      // 0,4,8,12
            const float4 v4 = *reinterpret_cast<const float4*>(
                &A[(size_t)(m0 + row) * lda + k0 + col]);
            float vv[4] = {v4.x, v4.y, v4.z, v4.w};
            if constexpr (MODE == MODE_PV) {
                const float mxv = mxp[m0 + row];
#pragma unroll
                for (int j = 0; j < 4; j++) vv[j] = __expf(vv[j] - mxv);
            }
#pragma unroll
            for (int j = 0; j < 4; j++) As[col + j][row] = vv[j];
        }
        // --- load B tile (BKD x BN) ---
        if constexpr (MODE == MODE_NN || MODE == MODE_PV) {
            const int row = tid >> 4;          // 0..15
            const int col = (tid & 15) * 4;    // 0..60
            const float4 v4 = *reinterpret_cast<const float4*>(
                &W[(size_t)(k0 + row) * ldw + n0 + col]);
            *reinterpret_cast<float4*>(&Bs[row][col]) = v4;
        } else {  // NT / SCORES : W[n, k]
            const int col  = tid >> 2;         // 0..63
            const int rowb = (tid & 3) * 4;    // 0,4,8,12
            const float4 v4 = *reinterpret_cast<const float4*>(
                &W[(size_t)(n0 + col) * ldw + k0 + rowb]);
            Bs[rowb + 0][col] = v4.x;
            Bs[rowb + 1][col] = v4.y;
            Bs[rowb + 2][col] = v4.z;
            Bs[rowb + 3][col] = v4.w;
        }
        __syncthreads();

#pragma unroll
        for (int kk = 0; kk < BKD; kk++) {
            float a[TM], bv[TN];
            const float4 a0 = *reinterpret_cast<const float4*>(&As[kk][ty * TM]);
            const float4 a1 = *reinterpret_cast<const float4*>(&As[kk][ty * TM + 4]);
            a[0] = a0.x; a[1] = a0.y; a[2] = a0.z; a[3] = a0.w;
            a[4] = a1.x; a[5] = a1.y; a[6] = a1.z; a[7] = a1.w;
            const float4 b0 = *reinterpret_cast<const float4*>(&Bs[kk][tx * TN]);
            bv[0] = b0.x; bv[1] = b0.y; bv[2] = b0.z; bv[3] = b0.w;
#pragma unroll
            for (int i = 0; i < TM; i++)
#pragma unroll
                for (int j = 0; j < TN; j++) acc[i][j] += a[i] * bv[j];
        }
        __syncthreads();
    }

    // --- epilogue ---
#pragma unroll
    for (int i = 0; i < TM; i++) {
        const int m = m0 + ty * TM + i;
        float rowscale = 1.f;
        if constexpr (MODE == MODE_PV) rowscale = invp[m];
        float vj[TN];
#pragma unroll
        for (int j = 0; j < TN; j++) {
            float val = acc[i][j];
            if constexpr (MODE == MODE_SCORES) val = val * 0.125f + maskp[n0 + tx * TN + j];
            if constexpr (MODE == MODE_PV)     val *= rowscale;
            if (bias) val += bias[n0 + tx * TN + j];
            vj[j] = val;
        }
        *reinterpret_cast<float4*>(&C[(size_t)m * ldc + n0 + tx * TN]) =
            make_float4(vj[0], vj[1], vj[2], vj[3]);
    }
}

// ---------------- softmax row stats (max, 1/sum) over stored scores ----------------
__global__ void __launch_bounds__(256) softmax_stats_k(const float* __restrict__ scores)
{
    __shared__ float red[256];
    const size_t r = blockIdx.x;
    const float4* rv = reinterpret_cast<const float4*>(scores + r * SS);
    const int t = threadIdx.x;

    float v[8];
    float mx = -1e30f;
#pragma unroll
    for (int i = 0; i < 2; i++) {
        const float4 q4 = rv[t + i * 256];
        v[i * 4 + 0] = q4.x; v[i * 4 + 1] = q4.y; v[i * 4 + 2] = q4.z; v[i * 4 + 3] = q4.w;
        mx = fmaxf(mx, fmaxf(fmaxf(q4.x, q4.y), fmaxf(q4.z, q4.w)));
    }
    red[t] = mx;
    __syncthreads();
    for (int s = 128; s > 0; s >>= 1) {
        if (t < s) red[t] = fmaxf(red[t], red[t + s]);
        __syncthreads();
    }
    mx = red[0];
    __syncthreads();

    float sum = 0.f;
#pragma unroll
    for (int i = 0; i < 8; i++) sum += __expf(v[i] - mx);
    red[t] = sum;
    __syncthreads();
    for (int s = 128; s > 0; s >>= 1) {
        if (t < s) red[t] += red[t + s];
        __syncthreads();
    }
    if (t == 0) { g_mx[r] = mx; g_inv[r] = 1.f / red[0]; }
}

// ---------------- depthwise conv along S (groups=HID), output transposed to [b,s,c] ----------------
__global__ void __launch_bounds__(256) dwconv_k(const float* __restrict__ x,
                                                const float* __restrict__ dwk)
{
    const int s = blockIdx.x;
    const int b = blockIdx.y;
    for (int c = threadIdx.x; c < HIDC; c += 256) {
        float acc = 0.f;
#pragma unroll
        for (int tp = 0; tp < KW; tp++) {
            const int sp = s + tp - KW / 2;
            if (sp >= 0 && sp < SS)
                acc += x[((size_t)b * SS + sp) * HIDC + c] * dwk[c * KW + tp];
        }
        g_dw[((size_t)b * SS + s) * HIDC + c] = acc;
    }
}

// ---------------- filter logits: (ks_out * q) @ Wak + bak ----------------
__global__ void __launch_bounds__(64) filt_logits_k(const float* __restrict__ Wak,
                                                    const float* __restrict__ bak)
{
    const int m = blockIdx.x;
    __shared__ float ca[AHSZ];
    const int t = threadIdx.x;
    for (int c = t; c < AHSZ; c += 64)
        ca[c] = g_ks[(size_t)m * AHSZ + c] * g_q[(size_t)m * AHSZ + c];
    __syncthreads();
    if (t < HK) {
        float s = 0.f;
        for (int c = 0; c < AHSZ; c++) s += ca[c] * Wak[c * HK + t];
        g_logits[(size_t)m * HK + t] = s + bak[t];
    }
}

// ---------------- softmax over K taps + windowed value conv ----------------
__global__ void __launch_bounds__(AHSZ) convout_k()
{
    const int m = blockIdx.x;
    const int b = m / SS;
    const int s = m % SS;
    __shared__ float filt[HK];
    const int t = threadIdx.x;   // 0..383

    if (t < NH) {
        float lg[KW];
        float mx = -1e30f;
#pragma unroll
        for (int i = 0; i < KW; i++) {
            lg[i] = g_logits[(size_t)m * HK + t * KW + i];
            mx = fmaxf(mx, lg[i]);
        }
        float sum = 0.f;
#pragma unroll
        for (int i = 0; i < KW; i++) { lg[i] = __expf(lg[i] - mx); sum += lg[i]; }
        const float is = 1.f / sum;
#pragma unroll
        for (int i = 0; i < KW; i++) filt[t * KW + i] = lg[i] * is;
    }
    __syncthreads();

    const int h = t / HD;
    float acc = 0.f;
#pragma unroll
    for (int tp = 0; tp < KW; tp++) {
        const int sp = s + tp - KW / 2;
        if (sp >= 0 && sp < SS)
            acc += g_v[((size_t)b * SS + sp) * AHSZ + t] * filt[h * KW + tp];
    }
    g_conv[(size_t)m * AHSZ + t] = acc;
}

// ---------------- launch ----------------
extern "C" void kernel_launch(void* const* d_in, const int* in_sizes, int n_in,
                              void* d_out, int out_size)
{
    const float* hidden = (const float*)d_in[0];
    const float* amask  = (const float*)d_in[1];
    const float* Wq = (const float*)d_in[2];  const float* bq = (const float*)d_in[3];
    const float* Wk = (const float*)d_in[4];  const float* bk = (const float*)d_in[5];
    const float* Wv = (const float*)d_in[6];  const float* bv = (const float*)d_in[7];
    const float* dwk = (const float*)d_in[8];
    const float* pw  = (const float*)d_in[9]; const float* sepb = (const float*)d_in[10];
    const float* Wak = (const float*)d_in[11]; const float* bak = (const float*)d_in[12];
    const float* Wsl = (const float*)d_in[13]; const float* bsl = (const float*)d_in[14];
    const float* Wcl = (const float*)d_in[15]; const float* bcl = (const float*)d_in[16];

    float *q, *k, *v, *dw, *ks, *cv, *attn_fb, *sco_fb;
    cudaGetSymbolAddress((void**)&q,  g_q);
    cudaGetSymbolAddress((void**)&k,  g_k);
    cudaGetSymbolAddress((void**)&v,  g_v);
    cudaGetSymbolAddress((void**)&dw, g_dw);
    cudaGetSymbolAddress((void**)&ks, g_ks);
    cudaGetSymbolAddress((void**)&cv, g_conv);
    cudaGetSymbolAddress((void**)&attn_fb, g_attn_fb);
    cudaGetSymbolAddress((void**)&sco_fb,  g_sco_fb);
    float *mxp, *invp;
    cudaGetSymbolAddress((void**)&mxp,  g_mx);
    cudaGetSymbolAddress((void**)&invp, g_inv);

    float* outp = (float*)d_out;
    const size_t CTX_SZ = (size_t)MROWS * HIDC;                 // 6291456
    const size_t ATT_OFF = CTX_SZ;
    const size_t ATT_SZ  = (size_t)MROWS * AHSZ;                // 3145728
    const size_t SCO_OFF = ATT_OFF + ATT_SZ;                    // 9437184
    const size_t SCO_SZ  = (size_t)NZ * SS * SS;                // 100663296

    float* attnp = ((size_t)out_size >= ATT_OFF + ATT_SZ) ? outp + ATT_OFF : attn_fb;
    float* scop  = ((size_t)out_size >= SCO_OFF + SCO_SZ) ? outp + SCO_OFF : sco_fb;

    const dim3 blk(NTHR);

    // 1) Q, K, V projections: [8192,768] @ [768,384]
    {
        const dim3 grd(AHSZ / BN, MROWS / BM);
        gemm_k<MODE_NN><<<grd, blk>>>(hidden, Wq, bq, q, HIDC, HIDC, AHSZ, AHSZ, nullptr, nullptr);
        gemm_k<MODE_NN><<<grd, blk>>>(hidden, Wk, bk, k, HIDC, HIDC, AHSZ, AHSZ, nullptr, nullptr);
        gemm_k<MODE_NN><<<grd, blk>>>(hidden, Wv, bv, v, HIDC, HIDC, AHSZ, AHSZ, nullptr, nullptr);
    }

    // 2) scores = QK^T/8 + mask -> out (batched over b,h)
    {
        const dim3 grd(SS / BN, SS / BM, NZ);
        gemm_k<MODE_SCORES><<<grd, blk>>>(q, k, nullptr, scop, 0, 0, 0, 0, amask, nullptr);
    }

    // 3) softmax row stats
    softmax_stats_k<<<NZ * SS, 256>>>(scop);

    // 4) ctx = softmax(scores) @ V, written directly as attn_output [b,s,h*64+d]
    {
        const dim3 grd(1, SS / BM, NZ);
        gemm_k<MODE_PV><<<grd, blk>>>(scop, v, nullptr, attnp, 0, 0, 0, 0, mxp, invp);
    }

    // 5) depthwise conv (transposed output [b,s,c])
    dwconv_k<<<dim3(SS, BB), 256>>>(hidden, dwk);

    // 6) pointwise: ks_out = dw @ pw^T + sep_bias   (pw is [AHS, HID] -> NT)
    {
        const dim3 grd(AHSZ / BN, MROWS / BM);
        gemm_k<MODE_NT><<<grd, blk>>>(dw, pw, sepb, ks, HIDC, HIDC, HIDC, AHSZ, nullptr, nullptr);
    }

    // 7) filter logits + 8) softmax over taps + windowed conv
    filt_logits_k<<<MROWS, 64>>>(Wak, bak);
    convout_k<<<MROWS, AHSZ>>>();

    // 9) mix: context = [attn@Wsl+bsl | conv@Wcl+bcl]
    {
        const dim3 grd(AHSZ / BN, MROWS / BM);
        gemm_k<MODE_NN><<<grd, blk>>>(attnp, Wsl, bsl, outp,        AHSZ, AHSZ, AHSZ, HIDC, nullptr, nullptr);
        gemm_k<MODE_NN><<<grd, blk>>>(cv,    Wcl, bcl, outp + AHSZ, AHSZ, AHSZ, AHSZ, HIDC, nullptr, nullptr);
    }
}